// round 2
// baseline (speedup 1.0000x reference)
#include <cuda_runtime.h>

#define NND 100000
#define DD 128
#define TT 3
#define EE 250000

static const long ND = (long)NND * DD;  // 12,800,000

// ---------------- scratch (device globals; no allocation allowed) ----------------
__device__ float g_S [(long)TT * NND * DD];   // per-etype scatter sums; later overwritten in-place by V_t
__device__ float g_Lg[(long)TT * NND * DD];   // attn logits contribution M_t @ wka_t
__device__ float g_bufA[(long)NND * DD];      // k / u
__device__ float g_bufB[(long)NND * DD];      // h / o
__device__ int   g_deg [TT * NND];
__device__ float g_rdeg[TT * NND];
__device__ float g_bnacc[2 * DD];
__device__ float g_bnscale[DD];
__device__ float g_bnshift[DD];
__device__ float g_wqa[2 * DD * DD];          // wq @ wa per attn layer
__device__ float g_wkwa[DD * DD];             // temp: wk @ wa
__device__ float g_wka[2 * TT * DD * DD];     // diag(emb_t) wk wa
__device__ float g_wvt[2 * TT * DD * DD];     // diag(emb_t) wv

__device__ __forceinline__ void red_add_v4(float* a, float4 v) {
    asm volatile("red.global.add.v4.f32 [%0], {%1,%2,%3,%4};"
                 :: "l"(a), "f"(v.x), "f"(v.y), "f"(v.z), "f"(v.w) : "memory");
}

// ---------------- elementwise / graph kernels ----------------
__global__ void gather_kernel(const float4* __restrict__ emb, const int* __restrict__ ind,
                              float4* __restrict__ out) {
    int i = blockIdx.x * blockDim.x + threadIdx.x;
    if (i >= NND * 32) return;
    int n = i >> 5, j = i & 31;
    out[i] = emb[(long)ind[n] * 32 + j];
}

__global__ void deg_kernel(const int* __restrict__ dst, int* __restrict__ deg) {
    int i = blockIdx.x * blockDim.x + threadIdx.x;
    if (i >= TT * EE) return;
    int t = i / EE;
    atomicAdd(&deg[t * NND + dst[i]], 1);
}

__global__ void rdeg_kernel(const int* __restrict__ deg, float* __restrict__ rdeg) {
    int i = blockIdx.x * blockDim.x + threadIdx.x;
    if (i >= TT * NND) return;
    int d = deg[i];
    rdeg[i] = d > 0 ? 1.0f / (float)d : 0.0f;
}

// one warp per edge: gather feat[src] row (512B) and vector-reduce into S[t][dst]
__global__ void scatter_kernel(const float4* __restrict__ feat, const int* __restrict__ src,
                               const int* __restrict__ dst, float* __restrict__ S) {
    int w = (blockIdx.x * blockDim.x + threadIdx.x) >> 5;
    int lane = threadIdx.x & 31;
    if (w >= TT * EE) return;
    int t = w / EE;
    int s = src[w], d = dst[w];
    float4 v = feat[(long)s * 32 + lane];
    red_add_v4(&S[((long)t * NND + d) * DD + (lane << 2)], v);
}

// GCN message reduce: k = (#etypes with deg>0)*feat - sum_t emb_t * S_t * rdeg_t
__global__ void kform_kernel(const float4* __restrict__ feat, const float4* __restrict__ S,
                             const int* __restrict__ deg, const float* __restrict__ rdeg,
                             const float4* __restrict__ eemb, float4* __restrict__ out) {
    int i = blockIdx.x * blockDim.x + threadIdx.x;
    if (i >= NND * 32) return;
    int n = i >> 5, j = i & 31;
    float cnt = (deg[n] > 0 ? 1.f : 0.f) + (deg[NND + n] > 0 ? 1.f : 0.f)
              + (deg[2 * NND + n] > 0 ? 1.f : 0.f);
    float4 f = feat[i];
    float4 acc = make_float4(cnt * f.x, cnt * f.y, cnt * f.z, cnt * f.w);
#pragma unroll
    for (int t = 0; t < TT; t++) {
        float r = rdeg[t * NND + n];
        float4 s = S[((long)t * NND + n) * 32 + j];
        float4 e = eemb[t * 32 + j];
        acc.x -= e.x * s.x * r;
        acc.y -= e.y * s.y * r;
        acc.z -= e.z * s.z * r;
        acc.w -= e.w * s.w * r;
    }
    out[i] = acc;
}

__global__ void bnstat_kernel(const float* __restrict__ h, int M, float* __restrict__ acc) {
    int c = threadIdx.x;  // 128 threads = 128 columns, coalesced row reads
    long m0 = (long)blockIdx.x * 128;
    long mend = m0 + 128; if (mend > M) mend = M;
    float s = 0.f, s2 = 0.f;
    for (long m = m0; m < mend; m++) {
        float v = h[m * DD + c];
        s += v; s2 += v * v;
    }
    atomicAdd(&acc[c], s);
    atomicAdd(&acc[DD + c], s2);
}

__global__ void bnfin_kernel(const float* __restrict__ acc, const float* __restrict__ gamma,
                             const float* __restrict__ beta, float minv,
                             float* __restrict__ scale, float* __restrict__ shift) {
    int c = threadIdx.x;
    float mu  = acc[c] * minv;
    float var = acc[DD + c] * minv - mu * mu;  // biased var (matches jnp.var)
    float isg = rsqrtf(var + 1e-5f);
    float sc = gamma[c] * isg;
    scale[c] = sc;
    shift[c] = beta[c] - mu * sc;
}

// softmax over etype axis (3 values) + weighted value combine, per (node, h)
__global__ void smx_kernel(const float* __restrict__ u, const float* __restrict__ L,
                           const float* __restrict__ V, const float* __restrict__ ba,
                           float* __restrict__ o) {
    long i = (long)blockIdx.x * blockDim.x + threadIdx.x;
    long nd = (long)NND * DD;
    if (i >= nd) return;
    int c = (int)(i & (DD - 1));
    float b = ba[c];
    float uu = u[i];
    float s0 = uu - L[i] + b;
    float s1 = uu - L[nd + i] + b;
    float s2 = uu - L[2 * nd + i] + b;
    float m = fmaxf(s0, fmaxf(s1, s2));
    float e0 = expf(s0 - m), e1 = expf(s1 - m), e2 = expf(s2 - m);
    float inv = 1.0f / (e0 + e1 + e2);
    o[i] = (e0 * V[i] + e1 * V[nd + i] + e2 * V[2 * nd + i]) * inv;
}

// wka_t = diag(emb_t) * (wk@wa),  wvt_t = diag(emb_t) * wv
__global__ void wscale_kernel(const float* __restrict__ eemb, const float* __restrict__ wkwa,
                              const float* __restrict__ wv, float* __restrict__ wka,
                              float* __restrict__ wvt) {
    int i = blockIdx.x * blockDim.x + threadIdx.x;
    if (i >= TT * DD * DD) return;
    int t = i >> 14;           // DD*DD = 16384
    int k = (i >> 7) & 127;
    float e = eemb[t * DD + k];
    int kn = i & (DD * DD - 1);
    wka[i] = e * wkwa[kn];
    wvt[i] = e * wv[kn];
}

// ---------------- fp32 SIMT GEMM: [M,128] @ [128,128] ----------------
// MA: 0 plain A, 1 A scaled per-row (mean normalize), 2 relu(A*colscale+colshift) (BN+relu)
// MC: 0 C = acc, 1 C = res + acc + bias  (residual epilogue)
// Note: C may alias A (in-place): each block reads only A-rows [m0,m0+64) and
// writes the same C-row range only after all its A reads are complete.
template<int MA, int MC>
__global__ void __launch_bounds__(128) gemm128(
    const float* __restrict__ A, const float* __restrict__ B, float* C, int M,
    long sAz, long sBz, long sCz,
    const float* __restrict__ rowscale, long sRSz,
    const float* __restrict__ ascale, const float* __restrict__ ashift,
    const float* res, const float* __restrict__ bias) {
    __shared__ float As[64][16];
    __shared__ float Bs[16][128];
    int z = blockIdx.z;
    A += (long)z * sAz; B += (long)z * sBz; C += (long)z * sCz;
    int tid = threadIdx.x;
    int m0 = blockIdx.x * 64;
    int tx = tid & 15, ty = tid >> 4;
    int row0 = ty * 8, col0 = tx * 8;
    int arow = tid >> 1, acol = (tid & 1) * 8;
    int brow = tid >> 3, bcol = (tid & 7) * 16;
    bool avalid = (m0 + arow) < M;
    float rs = 1.f;
    if (MA == 1) rs = avalid ? rowscale[(long)z * sRSz + m0 + arow] : 0.f;
    const float* Arow = A + (long)(m0 + arow) * DD;
    float acc[8][8];
#pragma unroll
    for (int i = 0; i < 8; i++)
#pragma unroll
        for (int j = 0; j < 8; j++) acc[i][j] = 0.f;

    for (int k0 = 0; k0 < DD; k0 += 16) {
        float4 av0 = make_float4(0.f, 0.f, 0.f, 0.f), av1 = av0;
        if (avalid) {
            av0 = *(const float4*)(Arow + k0 + acol);
            av1 = *(const float4*)(Arow + k0 + acol + 4);
        }
        if (MA == 1) {
            av0.x *= rs; av0.y *= rs; av0.z *= rs; av0.w *= rs;
            av1.x *= rs; av1.y *= rs; av1.z *= rs; av1.w *= rs;
        }
        if (MA == 2) {
            int c = k0 + acol;
            av0.x = fmaxf(av0.x * ascale[c + 0] + ashift[c + 0], 0.f);
            av0.y = fmaxf(av0.y * ascale[c + 1] + ashift[c + 1], 0.f);
            av0.z = fmaxf(av0.z * ascale[c + 2] + ashift[c + 2], 0.f);
            av0.w = fmaxf(av0.w * ascale[c + 3] + ashift[c + 3], 0.f);
            av1.x = fmaxf(av1.x * ascale[c + 4] + ashift[c + 4], 0.f);
            av1.y = fmaxf(av1.y * ascale[c + 5] + ashift[c + 5], 0.f);
            av1.z = fmaxf(av1.z * ascale[c + 6] + ashift[c + 6], 0.f);
            av1.w = fmaxf(av1.w * ascale[c + 7] + ashift[c + 7], 0.f);
        }
        *(float4*)&As[arow][acol] = av0;
        *(float4*)&As[arow][acol + 4] = av1;
#pragma unroll
        for (int q = 0; q < 4; q++)
            *(float4*)&Bs[brow][bcol + q * 4] =
                *(const float4*)&B[(long)(k0 + brow) * DD + bcol + q * 4];
        __syncthreads();
#pragma unroll
        for (int kk = 0; kk < 16; kk++) {
            float a[8];
#pragma unroll
            for (int i = 0; i < 8; i++) a[i] = As[row0 + i][kk];
            float4 b0 = *(float4*)&Bs[kk][col0];
            float4 b1 = *(float4*)&Bs[kk][col0 + 4];
            float bb[8] = {b0.x, b0.y, b0.z, b0.w, b1.x, b1.y, b1.z, b1.w};
#pragma unroll
            for (int i = 0; i < 8; i++)
#pragma unroll
                for (int j = 0; j < 8; j++) acc[i][j] += a[i] * bb[j];
        }
        __syncthreads();
    }
#pragma unroll
    for (int i = 0; i < 8; i++) {
        int m = m0 + row0 + i;
        if (m >= M) break;
        float out[8];
#pragma unroll
        for (int j = 0; j < 8; j++) out[j] = acc[i][j];
        if (MC == 1) {
            const float* rr = res + (long)m * DD + col0;
            float4 r0 = *(const float4*)(rr);
            float4 r1 = *(const float4*)(rr + 4);
            out[0] += r0.x + bias[col0 + 0]; out[1] += r0.y + bias[col0 + 1];
            out[2] += r0.z + bias[col0 + 2]; out[3] += r0.w + bias[col0 + 3];
            out[4] += r1.x + bias[col0 + 4]; out[5] += r1.y + bias[col0 + 5];
            out[6] += r1.z + bias[col0 + 6]; out[7] += r1.w + bias[col0 + 7];
        }
        *(float4*)(C + (long)m * DD + col0)     = make_float4(out[0], out[1], out[2], out[3]);
        *(float4*)(C + (long)m * DD + col0 + 4) = make_float4(out[4], out[5], out[6], out[7]);
    }
}

// ---------------- host orchestration ----------------
extern "C" void kernel_launch(void* const* d_in, const int* in_sizes, int n_in,
                              void* d_out, int out_size) {
    const float* n_emb = (const float*)d_in[0];
    const float* e_emb = (const float*)d_in[1];
    const float* m_w1[2]    = {(const float*)d_in[2],  (const float*)d_in[14]};
    const float* m_gamma[2] = {(const float*)d_in[3],  (const float*)d_in[15]};
    const float* m_beta[2]  = {(const float*)d_in[4],  (const float*)d_in[16]};
    const float* m_w2[2]    = {(const float*)d_in[5],  (const float*)d_in[17]};
    const float* m_b2[2]    = {(const float*)d_in[6],  (const float*)d_in[18]};
    const float* a_wq[2] = {(const float*)d_in[7],  (const float*)d_in[19]};
    const float* a_wk[2] = {(const float*)d_in[8],  (const float*)d_in[20]};
    const float* a_wv[2] = {(const float*)d_in[9],  (const float*)d_in[21]};
    const float* a_wa[2] = {(const float*)d_in[10], (const float*)d_in[22]};
    const float* a_ba[2] = {(const float*)d_in[11], (const float*)d_in[23]};
    const float* a_wp[2] = {(const float*)d_in[12], (const float*)d_in[24]};
    const float* a_bp[2] = {(const float*)d_in[13], (const float*)d_in[25]};
    const int* node_ind = (const int*)d_in[26];
    const int* esrc = (const int*)d_in[27];
    const int* edst = (const int*)d_in[28];
    float* feat = (float*)d_out;

    float *pS, *pL, *pA, *pB, *pRdeg, *pBnacc, *pBnscale, *pBnshift, *pWkwa, *pWqaB, *pWkaB, *pWvtB;
    int* pDeg;
    cudaGetSymbolAddress((void**)&pS, g_S);
    cudaGetSymbolAddress((void**)&pL, g_Lg);
    cudaGetSymbolAddress((void**)&pA, g_bufA);
    cudaGetSymbolAddress((void**)&pB, g_bufB);
    cudaGetSymbolAddress((void**)&pDeg, g_deg);
    cudaGetSymbolAddress((void**)&pRdeg, g_rdeg);
    cudaGetSymbolAddress((void**)&pBnacc, g_bnacc);
    cudaGetSymbolAddress((void**)&pBnscale, g_bnscale);
    cudaGetSymbolAddress((void**)&pBnshift, g_bnshift);
    cudaGetSymbolAddress((void**)&pWkwa, g_wkwa);
    cudaGetSymbolAddress((void**)&pWqaB, g_wqa);
    cudaGetSymbolAddress((void**)&pWkaB, g_wka);
    cudaGetSymbolAddress((void**)&pWvtB, g_wvt);

    const int gElem  = (NND * 32 + 255) / 256;        // 12500
    const int gDeg   = (TT * EE + 255) / 256;
    const int gRdeg  = (TT * NND + 255) / 256;
    const int gScat  = (TT * EE * 32) / 256;          // 93750 (exact)
    const int gGemm  = (NND + 63) / 64;               // 1563
    const int gBn    = (NND + 127) / 128;
    const int gSmx   = (int)((ND + 255) / 256);
    const int gWs    = (TT * DD * DD + 255) / 256;
    const size_t Sbytes = (size_t)TT * NND * DD * sizeof(float);

    // ---- init: feat = n_emb[node_ind]; degrees; e_emb passthrough output ----
    gather_kernel<<<gElem, 256>>>((const float4*)n_emb, node_ind, (float4*)feat);
    cudaMemcpyAsync(feat + ND, e_emb, TT * DD * sizeof(float), cudaMemcpyDeviceToDevice, 0);
    cudaMemsetAsync(pDeg, 0, TT * NND * sizeof(int), 0);
    deg_kernel<<<gDeg, 256>>>(edst, pDeg);
    rdeg_kernel<<<gRdeg, 256>>>(pDeg, pRdeg);

    // ---- precompute folded attention weights for both attn layers ----
    for (int l = 0; l < 2; l++) {
        float* pWqa = pWqaB + (long)l * DD * DD;
        float* pWka = pWkaB + (long)l * TT * DD * DD;
        float* pWvt = pWvtB + (long)l * TT * DD * DD;
        gemm128<0, 0><<<2, 128>>>(a_wq[l], a_wa[l], pWqa, DD, 0, 0, 0,
                                  nullptr, 0, nullptr, nullptr, nullptr, nullptr);
        gemm128<0, 0><<<2, 128>>>(a_wk[l], a_wa[l], pWkwa, DD, 0, 0, 0,
                                  nullptr, 0, nullptr, nullptr, nullptr, nullptr);
        wscale_kernel<<<gWs, 256>>>(e_emb, pWkwa, a_wv[l], pWka, pWvt);
    }

    // ---- 4 layers: GCN, attn, GCN, attn ----
    for (int l = 0; l < 2; l++) {
        // GCN layer l
        cudaMemsetAsync(pS, 0, Sbytes, 0);
        scatter_kernel<<<gScat, 256>>>((const float4*)feat, esrc, edst, pS);
        kform_kernel<<<gElem, 256>>>((const float4*)feat, (const float4*)pS, pDeg, pRdeg,
                                     (const float4*)e_emb, (float4*)pA);
        gemm128<0, 0><<<gGemm, 128>>>(pA, m_w1[l], pB, NND, 0, 0, 0,
                                      nullptr, 0, nullptr, nullptr, nullptr, nullptr);
        cudaMemsetAsync(pBnacc, 0, 2 * DD * sizeof(float), 0);
        bnstat_kernel<<<gBn, 128>>>(pB, NND, pBnacc);
        bnfin_kernel<<<1, 128>>>(pBnacc, m_gamma[l], m_beta[l], 1.0f / NND, pBnscale, pBnshift);
        gemm128<2, 1><<<gGemm, 128>>>(pB, m_w2[l], feat, NND, 0, 0, 0,
                                      nullptr, 0, pBnscale, pBnshift, feat, m_b2[l]);

        // attention layer l
        const float* pWqa = pWqaB + (long)l * DD * DD;
        const float* pWka = pWkaB + (long)l * TT * DD * DD;
        const float* pWvt = pWvtB + (long)l * TT * DD * DD;
        cudaMemsetAsync(pS, 0, Sbytes, 0);
        scatter_kernel<<<gScat, 256>>>((const float4*)feat, esrc, edst, pS);
        gemm128<0, 0><<<gGemm, 128>>>(feat, pWqa, pA, NND, 0, 0, 0,
                                      nullptr, 0, nullptr, nullptr, nullptr, nullptr);  // u
        dim3 gz(gGemm, 1, TT);
        // L_t first (reads S), then V_t in-place over S (C aliases A per-block safely)
        gemm128<1, 0><<<gz, 128>>>(pS, pWka, pL, NND, ND, (long)DD * DD, ND,
                                   pRdeg, NND, nullptr, nullptr, nullptr, nullptr);     // L_t
        gemm128<1, 0><<<gz, 128>>>(pS, pWvt, pS, NND, ND, (long)DD * DD, ND,
                                   pRdeg, NND, nullptr, nullptr, nullptr, nullptr);     // V_t (in-place)
        smx_kernel<<<gSmx, 256>>>(pA, pL, pS, a_ba[l], pB);                             // o
        gemm128<0, 1><<<gGemm, 128>>>(pB, a_wp[l], feat, NND, 0, 0, 0,
                                      nullptr, 0, nullptr, nullptr, feat, a_bp[l]);     // residual out
    }
}

// round 5
// speedup vs baseline: 1.5710x; 1.5710x over previous
#include <cuda_runtime.h>

#define NND 100000
#define DD 128
#define TT 3
#define EE 250000

static const long ND = (long)NND * DD;  // 12,800,000

// ---------------- scratch (device globals; no allocation allowed) ----------------
__device__ float g_S [(long)TT * NND * DD];   // per-etype scatter sums; later overwritten in-place by V_t
__device__ float g_Lg[(long)TT * NND * DD];   // attn logits contribution M_t @ wka_t
__device__ float g_bufA[(long)NND * DD];      // k / u
__device__ float g_bufB[(long)NND * DD];      // h / o
__device__ int   g_deg [TT * NND];
__device__ float g_rdeg[TT * NND];
__device__ float g_bnacc[2 * DD];
__device__ float g_bnscale[DD];
__device__ float g_bnshift[DD];
__device__ float g_wqa[2 * DD * DD];          // wq @ wa per attn layer
__device__ float g_wkwa[DD * DD];             // temp: wk @ wa
__device__ float g_wka[2 * TT * DD * DD];     // diag(emb_t) wk wa
__device__ float g_wvt[2 * TT * DD * DD];     // diag(emb_t) wv

__device__ __forceinline__ void red_add_v4(float* a, float4 v) {
    asm volatile("red.global.add.v4.f32 [%0], {%1,%2,%3,%4};"
                 :: "l"(a), "f"(v.x), "f"(v.y), "f"(v.z), "f"(v.w) : "memory");
}

__device__ __forceinline__ unsigned f2tf32(float f) {
    unsigned o;
    asm("cvt.rna.tf32.f32 %0, %1;" : "=r"(o) : "f"(f));
    return o;
}

__device__ __forceinline__ void mma_tf32(float* c, const unsigned* a, unsigned b0, unsigned b1) {
    asm volatile(
        "mma.sync.aligned.m16n8k8.row.col.f32.tf32.tf32.f32 "
        "{%0,%1,%2,%3}, {%4,%5,%6,%7}, {%8,%9}, {%0,%1,%2,%3};"
        : "+f"(c[0]), "+f"(c[1]), "+f"(c[2]), "+f"(c[3])
        : "r"(a[0]), "r"(a[1]), "r"(a[2]), "r"(a[3]), "r"(b0), "r"(b1));
}

// ---------------- elementwise / graph kernels ----------------
__global__ void gather_kernel(const float4* __restrict__ emb, const int* __restrict__ ind,
                              float4* __restrict__ out) {
    int i = blockIdx.x * blockDim.x + threadIdx.x;
    if (i >= NND * 32) return;
    int n = i >> 5, j = i & 31;
    out[i] = emb[(long)ind[n] * 32 + j];
}

__global__ void deg_kernel(const int* __restrict__ dst, int* __restrict__ deg) {
    int i = blockIdx.x * blockDim.x + threadIdx.x;
    if (i >= TT * EE) return;
    int t = i / EE;
    atomicAdd(&deg[t * NND + dst[i]], 1);
}

__global__ void rdeg_kernel(const int* __restrict__ deg, float* __restrict__ rdeg) {
    int i = blockIdx.x * blockDim.x + threadIdx.x;
    if (i >= TT * NND) return;
    int d = deg[i];
    rdeg[i] = d > 0 ? 1.0f / (float)d : 0.0f;
}

// one warp per edge: gather feat[src] row (512B) and vector-reduce into S[t][dst]
__global__ void scatter_kernel(const float4* __restrict__ feat, const int* __restrict__ src,
                               const int* __restrict__ dst, float* __restrict__ S) {
    int w = (blockIdx.x * blockDim.x + threadIdx.x) >> 5;
    int lane = threadIdx.x & 31;
    if (w >= TT * EE) return;
    int t = w / EE;
    int s = src[w], d = dst[w];
    float4 v = feat[(long)s * 32 + lane];
    red_add_v4(&S[((long)t * NND + d) * DD + (lane << 2)], v);
}

// GCN message reduce: k = (#etypes with deg>0)*feat - sum_t emb_t * S_t * rdeg_t
__global__ void kform_kernel(const float4* __restrict__ feat, const float4* __restrict__ S,
                             const int* __restrict__ deg, const float* __restrict__ rdeg,
                             const float4* __restrict__ eemb, float4* __restrict__ out) {
    int i = blockIdx.x * blockDim.x + threadIdx.x;
    if (i >= NND * 32) return;
    int n = i >> 5, j = i & 31;
    float cnt = (deg[n] > 0 ? 1.f : 0.f) + (deg[NND + n] > 0 ? 1.f : 0.f)
              + (deg[2 * NND + n] > 0 ? 1.f : 0.f);
    float4 f = feat[i];
    float4 acc = make_float4(cnt * f.x, cnt * f.y, cnt * f.z, cnt * f.w);
#pragma unroll
    for (int t = 0; t < TT; t++) {
        float r = rdeg[t * NND + n];
        float4 s = S[((long)t * NND + n) * 32 + j];
        float4 e = eemb[t * 32 + j];
        acc.x -= e.x * s.x * r;
        acc.y -= e.y * s.y * r;
        acc.z -= e.z * s.z * r;
        acc.w -= e.w * s.w * r;
    }
    out[i] = acc;
}

__global__ void bnstat_kernel(const float* __restrict__ h, int M, float* __restrict__ acc) {
    int c = threadIdx.x;  // 128 threads = 128 columns, coalesced row reads
    long m0 = (long)blockIdx.x * 128;
    long mend = m0 + 128; if (mend > M) mend = M;
    float s = 0.f, s2 = 0.f;
    for (long m = m0; m < mend; m++) {
        float v = h[m * DD + c];
        s += v; s2 += v * v;
    }
    atomicAdd(&acc[c], s);
    atomicAdd(&acc[DD + c], s2);
}

__global__ void bnfin_kernel(const float* __restrict__ acc, const float* __restrict__ gamma,
                             const float* __restrict__ beta, float minv,
                             float* __restrict__ scale, float* __restrict__ shift) {
    int c = threadIdx.x;
    float mu  = acc[c] * minv;
    float var = acc[DD + c] * minv - mu * mu;  // biased var (matches jnp.var)
    float isg = rsqrtf(var + 1e-5f);
    float sc = gamma[c] * isg;
    scale[c] = sc;
    shift[c] = beta[c] - mu * sc;
}

// softmax over etype axis (3 values) + weighted value combine, per (node, h)
__global__ void smx_kernel(const float* __restrict__ u, const float* __restrict__ L,
                           const float* __restrict__ V, const float* __restrict__ ba,
                           float* __restrict__ o) {
    long i = (long)blockIdx.x * blockDim.x + threadIdx.x;
    long nd = (long)NND * DD;
    if (i >= nd) return;
    int c = (int)(i & (DD - 1));
    float b = ba[c];
    float uu = u[i];
    float s0 = uu - L[i] + b;
    float s1 = uu - L[nd + i] + b;
    float s2 = uu - L[2 * nd + i] + b;
    float m = fmaxf(s0, fmaxf(s1, s2));
    float e0 = expf(s0 - m), e1 = expf(s1 - m), e2 = expf(s2 - m);
    float inv = 1.0f / (e0 + e1 + e2);
    o[i] = (e0 * V[i] + e1 * V[nd + i] + e2 * V[2 * nd + i]) * inv;
}

// wka_t = diag(emb_t) * (wk@wa),  wvt_t = diag(emb_t) * wv
__global__ void wscale_kernel(const float* __restrict__ eemb, const float* __restrict__ wkwa,
                              const float* __restrict__ wv, float* __restrict__ wka,
                              float* __restrict__ wvt) {
    int i = blockIdx.x * blockDim.x + threadIdx.x;
    if (i >= TT * DD * DD) return;
    int t = i >> 14;           // DD*DD = 16384
    int k = (i >> 7) & 127;
    float e = eemb[t * DD + k];
    int kn = i & (DD * DD - 1);
    wka[i] = e * wkwa[kn];
    wvt[i] = e * wv[kn];
}

// ---------------- tf32 tensor-core GEMM: [M,128] @ [128,128] ----------------
// CTA tile 128x128, 256 threads (8 warps, 4x2), warp tile 32x64, mma m16n8k8.
// MA: 0 plain A, 1 A scaled per-row, 2 relu(A*colscale+colshift)  (applied at smem store)
// MC: 0 C = acc, 1 C = res + acc + bias
// C may alias A: each block reads only A-rows [m0,m0+128) (all reads complete
// before the epilogue) and writes the same row range.
#define AS_LD 36
#define BS_LD 136
template<int MA, int MC>
__global__ void __launch_bounds__(256) gemm_tc(
    const float* __restrict__ A, const float* __restrict__ B, float* C, int M,
    long sAz, long sBz, long sCz,
    const float* __restrict__ rowscale, long sRSz,
    const float* __restrict__ ascale, const float* __restrict__ ashift,
    const float* res, const float* __restrict__ bias) {
    __shared__ unsigned As[128 * AS_LD];
    __shared__ unsigned Bs[32 * BS_LD];
    int z = blockIdx.z;
    A += (long)z * sAz; B += (long)z * sBz; C += (long)z * sCz;
    int tid = threadIdx.x;
    int warp = tid >> 5, lane = tid & 31;
    int wm = warp & 3, wn = warp >> 2;           // warp tile: rows wm*32, cols wn*64
    int r = lane >> 2, cq = lane & 3;
    int m0 = blockIdx.x * 128;

    // A loader: 2 threads per row, 16 floats each
    int arow = tid >> 1;
    int acol = (tid & 1) * 16;
    bool avalid = (m0 + arow) < M;
    float rs = 1.f;
    if (MA == 1) rs = avalid ? rowscale[(long)z * sRSz + m0 + arow] : 0.f;
    const float* Ap = A + (long)(m0 + arow) * DD + acol;
    // B loader: 32 rows x 128 cols per chunk, 16 floats/thread
    int brow = tid >> 3;
    int bcol = (tid & 7) * 16;
    const float* Bp = B + (long)brow * DD + bcol;

    float acc[2][8][4];
#pragma unroll
    for (int i = 0; i < 2; i++)
#pragma unroll
        for (int j = 0; j < 8; j++)
#pragma unroll
            for (int q = 0; q < 4; q++) acc[i][j][q] = 0.f;

    for (int k0 = 0; k0 < DD; k0 += 32) {
        // ---- stage A chunk [128 x 32] ----
        {
            float av[16];
            if (avalid) {
#pragma unroll
                for (int q = 0; q < 4; q++)
                    *(float4*)&av[q * 4] = *(const float4*)(Ap + k0 + q * 4);
                if (MA == 1) {
#pragma unroll
                    for (int j = 0; j < 16; j++) av[j] *= rs;
                }
                if (MA == 2) {
#pragma unroll
                    for (int j = 0; j < 16; j++) {
                        int c = k0 + acol + j;
                        av[j] = fmaxf(av[j] * ascale[c] + ashift[c], 0.f);
                    }
                }
            } else {
#pragma unroll
                for (int j = 0; j < 16; j++) av[j] = 0.f;
            }
            unsigned* dst = &As[arow * AS_LD + acol];
#pragma unroll
            for (int j = 0; j < 16; j++) dst[j] = f2tf32(av[j]);
        }
        // ---- stage B chunk [32 x 128] ----
        {
            float bv[16];
#pragma unroll
            for (int q = 0; q < 4; q++)
                *(float4*)&bv[q * 4] = *(const float4*)(Bp + (long)k0 * DD + q * 4);
            unsigned* dst = &Bs[brow * BS_LD + bcol];
#pragma unroll
            for (int j = 0; j < 16; j++) dst[j] = f2tf32(bv[j]);
        }
        __syncthreads();
#pragma unroll
        for (int kk = 0; kk < 32; kk += 8) {
            unsigned af[2][4];
#pragma unroll
            for (int i = 0; i < 2; i++) {
                int base = (wm * 32 + i * 16 + r) * AS_LD + kk + cq;
                af[i][0] = As[base];
                af[i][1] = As[base + 8 * AS_LD];
                af[i][2] = As[base + 4];
                af[i][3] = As[base + 8 * AS_LD + 4];
            }
#pragma unroll
            for (int j = 0; j < 8; j++) {
                int cb = wn * 64 + j * 8 + r;
                unsigned b0 = Bs[(kk + cq) * BS_LD + cb];
                unsigned b1 = Bs[(kk + cq + 4) * BS_LD + cb];
                mma_tf32(acc[0][j], af[0], b0, b1);
                mma_tf32(acc[1][j], af[1], b0, b1);
            }
        }
        __syncthreads();
    }

    // ---- epilogue: c0/c1 at (row, col..col+1), c2/c3 at (row+8, same cols) ----
#pragma unroll
    for (int i = 0; i < 2; i++) {
        int mr0 = m0 + wm * 32 + i * 16 + r;
#pragma unroll
        for (int h = 0; h < 2; h++) {
            int m = mr0 + h * 8;
            if (m >= M) continue;
            float* Crow = C + (long)m * DD;
            const float* Rrow = (MC == 1) ? res + (long)m * DD : nullptr;
#pragma unroll
            for (int j = 0; j < 8; j++) {
                int col = wn * 64 + j * 8 + cq * 2;
                float o0 = acc[i][j][h * 2 + 0];
                float o1 = acc[i][j][h * 2 + 1];
                if (MC == 1) {
                    float2 rr = *(const float2*)(Rrow + col);
                    o0 += rr.x + bias[col];
                    o1 += rr.y + bias[col + 1];
                }
                *(float2*)(Crow + col) = make_float2(o0, o1);
            }
        }
    }
}

// ---------------- host orchestration ----------------
extern "C" void kernel_launch(void* const* d_in, const int* in_sizes, int n_in,
                              void* d_out, int out_size) {
    const float* n_emb = (const float*)d_in[0];
    const float* e_emb = (const float*)d_in[1];
    const float* m_w1[2]    = {(const float*)d_in[2],  (const float*)d_in[14]};
    const float* m_gamma[2] = {(const float*)d_in[3],  (const float*)d_in[15]};
    const float* m_beta[2]  = {(const float*)d_in[4],  (const float*)d_in[16]};
    const float* m_w2[2]    = {(const float*)d_in[5],  (const float*)d_in[17]};
    const float* m_b2[2]    = {(const float*)d_in[6],  (const float*)d_in[18]};
    const float* a_wq[2] = {(const float*)d_in[7],  (const float*)d_in[19]};
    const float* a_wk[2] = {(const float*)d_in[8],  (const float*)d_in[20]};
    const float* a_wv[2] = {(const float*)d_in[9],  (const float*)d_in[21]};
    const float* a_wa[2] = {(const float*)d_in[10], (const float*)d_in[22]};
    const float* a_ba[2] = {(const float*)d_in[11], (const float*)d_in[23]};
    const float* a_wp[2] = {(const float*)d_in[12], (const float*)d_in[24]};
    const float* a_bp[2] = {(const float*)d_in[13], (const float*)d_in[25]};
    const int* node_ind = (const int*)d_in[26];
    const int* esrc = (const int*)d_in[27];
    const int* edst = (const int*)d_in[28];
    float* feat = (float*)d_out;

    float *pS, *pL, *pA, *pB, *pRdeg, *pBnacc, *pBnscale, *pBnshift, *pWkwa, *pWqaB, *pWkaB, *pWvtB;
    int* pDeg;
    cudaGetSymbolAddress((void**)&pS, g_S);
    cudaGetSymbolAddress((void**)&pL, g_Lg);
    cudaGetSymbolAddress((void**)&pA, g_bufA);
    cudaGetSymbolAddress((void**)&pB, g_bufB);
    cudaGetSymbolAddress((void**)&pDeg, g_deg);
    cudaGetSymbolAddress((void**)&pRdeg, g_rdeg);
    cudaGetSymbolAddress((void**)&pBnacc, g_bnacc);
    cudaGetSymbolAddress((void**)&pBnscale, g_bnscale);
    cudaGetSymbolAddress((void**)&pBnshift, g_bnshift);
    cudaGetSymbolAddress((void**)&pWkwa, g_wkwa);
    cudaGetSymbolAddress((void**)&pWqaB, g_wqa);
    cudaGetSymbolAddress((void**)&pWkaB, g_wka);
    cudaGetSymbolAddress((void**)&pWvtB, g_wvt);

    const int gElem  = (NND * 32 + 255) / 256;        // 12500
    const int gDeg   = (TT * EE + 255) / 256;
    const int gRdeg  = (TT * NND + 255) / 256;
    const int gScat  = (TT * EE * 32) / 256;          // 93750 (exact)
    const int gGemm  = (NND + 127) / 128;             // 782
    const int gBn    = (NND + 127) / 128;
    const int gSmx   = (int)((ND + 255) / 256);
    const int gWs    = (TT * DD * DD + 255) / 256;
    const size_t Sbytes = (size_t)TT * NND * DD * sizeof(float);

    // ---- init: feat = n_emb[node_ind]; degrees; e_emb passthrough output ----
    gather_kernel<<<gElem, 256>>>((const float4*)n_emb, node_ind, (float4*)feat);
    cudaMemcpyAsync(feat + ND, e_emb, TT * DD * sizeof(float), cudaMemcpyDeviceToDevice, 0);
    cudaMemsetAsync(pDeg, 0, TT * NND * sizeof(int), 0);
    deg_kernel<<<gDeg, 256>>>(edst, pDeg);
    rdeg_kernel<<<gRdeg, 256>>>(pDeg, pRdeg);

    // ---- precompute folded attention weights for both attn layers ----
    for (int l = 0; l < 2; l++) {
        float* pWqa = pWqaB + (long)l * DD * DD;
        float* pWka = pWkaB + (long)l * TT * DD * DD;
        float* pWvt = pWvtB + (long)l * TT * DD * DD;
        gemm_tc<0, 0><<<1, 256>>>(a_wq[l], a_wa[l], pWqa, DD, 0, 0, 0,
                                  nullptr, 0, nullptr, nullptr, nullptr, nullptr);
        gemm_tc<0, 0><<<1, 256>>>(a_wk[l], a_wa[l], pWkwa, DD, 0, 0, 0,
                                  nullptr, 0, nullptr, nullptr, nullptr, nullptr);
        wscale_kernel<<<gWs, 256>>>(e_emb, pWkwa, a_wv[l], pWka, pWvt);
    }

    // ---- 4 layers: GCN, attn, GCN, attn ----
    for (int l = 0; l < 2; l++) {
        // GCN layer l
        cudaMemsetAsync(pS, 0, Sbytes, 0);
        scatter_kernel<<<gScat, 256>>>((const float4*)feat, esrc, edst, pS);
        kform_kernel<<<gElem, 256>>>((const float4*)feat, (const float4*)pS, pDeg, pRdeg,
                                     (const float4*)e_emb, (float4*)pA);
        gemm_tc<0, 0><<<gGemm, 256>>>(pA, m_w1[l], pB, NND, 0, 0, 0,
                                      nullptr, 0, nullptr, nullptr, nullptr, nullptr);
        cudaMemsetAsync(pBnacc, 0, 2 * DD * sizeof(float), 0);
        bnstat_kernel<<<gBn, 128>>>(pB, NND, pBnacc);
        bnfin_kernel<<<1, 128>>>(pBnacc, m_gamma[l], m_beta[l], 1.0f / NND, pBnscale, pBnshift);
        gemm_tc<2, 1><<<gGemm, 256>>>(pB, m_w2[l], feat, NND, 0, 0, 0,
                                      nullptr, 0, pBnscale, pBnshift, feat, m_b2[l]);

        // attention layer l
        const float* pWqa = pWqaB + (long)l * DD * DD;
        const float* pWka = pWkaB + (long)l * TT * DD * DD;
        const float* pWvt = pWvtB + (long)l * TT * DD * DD;
        cudaMemsetAsync(pS, 0, Sbytes, 0);
        scatter_kernel<<<gScat, 256>>>((const float4*)feat, esrc, edst, pS);
        gemm_tc<0, 0><<<gGemm, 256>>>(feat, pWqa, pA, NND, 0, 0, 0,
                                      nullptr, 0, nullptr, nullptr, nullptr, nullptr);  // u
        dim3 gz(gGemm, 1, TT);
        // L_t first (reads S), then V_t in-place over S
        gemm_tc<1, 0><<<gz, 256>>>(pS, pWka, pL, NND, ND, (long)DD * DD, ND,
                                   pRdeg, NND, nullptr, nullptr, nullptr, nullptr);     // L_t
        gemm_tc<1, 0><<<gz, 256>>>(pS, pWvt, pS, NND, ND, (long)DD * DD, ND,
                                   pRdeg, NND, nullptr, nullptr, nullptr, nullptr);     // V_t (in-place)
        smx_kernel<<<gSmx, 256>>>(pA, pL, pS, a_ba[l], pB);                             // o
        gemm_tc<0, 1><<<gGemm, 256>>>(pB, a_wp[l], feat, NND, 0, 0, 0,
                                      nullptr, 0, nullptr, nullptr, feat, a_bp[l]);     // residual out
    }
}

// round 6
// speedup vs baseline: 1.5720x; 1.0006x over previous
#include <cuda_runtime.h>

#define NND 100000
#define DD 128
#define TT 3
#define EE 250000

static const long ND = (long)NND * DD;  // 12,800,000

// ---------------- scratch (device globals; no allocation allowed) ----------------
__device__ float g_S [(long)TT * NND * DD];   // per-etype scatter sums; later overwritten in-place by V_t
__device__ float g_Lg[(long)TT * NND * DD];   // attn logits contribution M_t @ wka_t
__device__ float g_bufA[(long)NND * DD];      // k / u
__device__ float g_bufB[(long)NND * DD];      // h / o
__device__ int   g_deg [TT * NND];
__device__ float g_rdeg[TT * NND];
__device__ float g_bnacc[2 * DD];
__device__ float g_bnscale[DD];
__device__ float g_bnshift[DD];
__device__ float g_wqa[2 * DD * DD];          // wq @ wa per attn layer
__device__ float g_wkwa[DD * DD];             // temp: wk @ wa
__device__ float g_wka[2 * TT * DD * DD];     // diag(emb_t) wk wa
__device__ float g_wvt[2 * TT * DD * DD];     // diag(emb_t) wv

__device__ __forceinline__ void red_add_v4(float* a, float4 v) {
    asm volatile("red.global.add.v4.f32 [%0], {%1,%2,%3,%4};"
                 :: "l"(a), "f"(v.x), "f"(v.y), "f"(v.z), "f"(v.w) : "memory");
}

__device__ __forceinline__ unsigned f2tf32(float f) {
    unsigned o;
    asm("cvt.rna.tf32.f32 %0, %1;" : "=r"(o) : "f"(f));
    return o;
}

__device__ __forceinline__ void mma_tf32(float* c, const unsigned* a, unsigned b0, unsigned b1) {
    asm volatile(
        "mma.sync.aligned.m16n8k8.row.col.f32.tf32.tf32.f32 "
        "{%0,%1,%2,%3}, {%4,%5,%6,%7}, {%8,%9}, {%0,%1,%2,%3};"
        : "+f"(c[0]), "+f"(c[1]), "+f"(c[2]), "+f"(c[3])
        : "r"(a[0]), "r"(a[1]), "r"(a[2]), "r"(a[3]), "r"(b0), "r"(b1));
}

// ---------------- elementwise / graph kernels ----------------
__global__ void gather_kernel(const float4* __restrict__ emb, const int* __restrict__ ind,
                              float4* __restrict__ out) {
    int i = blockIdx.x * blockDim.x + threadIdx.x;
    if (i >= NND * 32) return;
    int n = i >> 5, j = i & 31;
    out[i] = emb[(long)ind[n] * 32 + j];
}

__global__ void deg_kernel(const int* __restrict__ dst, int* __restrict__ deg) {
    int i = blockIdx.x * blockDim.x + threadIdx.x;
    if (i >= TT * EE) return;
    int t = i / EE;
    atomicAdd(&deg[t * NND + dst[i]], 1);
}

__global__ void rdeg_kernel(const int* __restrict__ deg, float* __restrict__ rdeg) {
    int i = blockIdx.x * blockDim.x + threadIdx.x;
    if (i >= TT * NND) return;
    int d = deg[i];
    rdeg[i] = d > 0 ? 1.0f / (float)d : 0.0f;
}

// one warp per edge: gather feat[src] row (512B) and vector-reduce into S[t][dst]
__global__ void scatter_kernel(const float4* __restrict__ feat, const int* __restrict__ src,
                               const int* __restrict__ dst, float* __restrict__ S) {
    int w = (blockIdx.x * blockDim.x + threadIdx.x) >> 5;
    int lane = threadIdx.x & 31;
    if (w >= TT * EE) return;
    int t = w / EE;
    int s = src[w], d = dst[w];
    float4 v = feat[(long)s * 32 + lane];
    red_add_v4(&S[((long)t * NND + d) * DD + (lane << 2)], v);
}

// GCN message reduce: k = (#etypes with deg>0)*feat - sum_t emb_t * S_t * rdeg_t
__global__ void kform_kernel(const float4* __restrict__ feat, const float4* __restrict__ S,
                             const int* __restrict__ deg, const float* __restrict__ rdeg,
                             const float4* __restrict__ eemb, float4* __restrict__ out) {
    int i = blockIdx.x * blockDim.x + threadIdx.x;
    if (i >= NND * 32) return;
    int n = i >> 5, j = i & 31;
    float cnt = (deg[n] > 0 ? 1.f : 0.f) + (deg[NND + n] > 0 ? 1.f : 0.f)
              + (deg[2 * NND + n] > 0 ? 1.f : 0.f);
    float4 f = feat[i];
    float4 acc = make_float4(cnt * f.x, cnt * f.y, cnt * f.z, cnt * f.w);
#pragma unroll
    for (int t = 0; t < TT; t++) {
        float r = rdeg[t * NND + n];
        float4 s = S[((long)t * NND + n) * 32 + j];
        float4 e = eemb[t * 32 + j];
        acc.x -= e.x * s.x * r;
        acc.y -= e.y * s.y * r;
        acc.z -= e.z * s.z * r;
        acc.w -= e.w * s.w * r;
    }
    out[i] = acc;
}

__global__ void bnstat_kernel(const float* __restrict__ h, int M, float* __restrict__ acc) {
    int c = threadIdx.x;  // 128 threads = 128 columns, coalesced row reads
    long m0 = (long)blockIdx.x * 128;
    long mend = m0 + 128; if (mend > M) mend = M;
    float s = 0.f, s2 = 0.f;
    for (long m = m0; m < mend; m++) {
        float v = h[m * DD + c];
        s += v; s2 += v * v;
    }
    atomicAdd(&acc[c], s);
    atomicAdd(&acc[DD + c], s2);
}

__global__ void bnfin_kernel(const float* __restrict__ acc, const float* __restrict__ gamma,
                             const float* __restrict__ beta, float minv,
                             float* __restrict__ scale, float* __restrict__ shift) {
    int c = threadIdx.x;
    float mu  = acc[c] * minv;
    float var = acc[DD + c] * minv - mu * mu;  // biased var (matches jnp.var)
    float isg = rsqrtf(var + 1e-5f);
    float sc = gamma[c] * isg;
    scale[c] = sc;
    shift[c] = beta[c] - mu * sc;
}

// softmax over etype axis (3 values) + weighted value combine, per (node, h)
__global__ void smx_kernel(const float* __restrict__ u, const float* __restrict__ L,
                           const float* __restrict__ V, const float* __restrict__ ba,
                           float* __restrict__ o) {
    long i = (long)blockIdx.x * blockDim.x + threadIdx.x;
    long nd = (long)NND * DD;
    if (i >= nd) return;
    int c = (int)(i & (DD - 1));
    float b = ba[c];
    float uu = u[i];
    float s0 = uu - L[i] + b;
    float s1 = uu - L[nd + i] + b;
    float s2 = uu - L[2 * nd + i] + b;
    float m = fmaxf(s0, fmaxf(s1, s2));
    float e0 = expf(s0 - m), e1 = expf(s1 - m), e2 = expf(s2 - m);
    float inv = 1.0f / (e0 + e1 + e2);
    o[i] = (e0 * V[i] + e1 * V[nd + i] + e2 * V[2 * nd + i]) * inv;
}

// wka_t = diag(emb_t) * (wk@wa),  wvt_t = diag(emb_t) * wv
__global__ void wscale_kernel(const float* __restrict__ eemb, const float* __restrict__ wkwa,
                              const float* __restrict__ wv, float* __restrict__ wka,
                              float* __restrict__ wvt) {
    int i = blockIdx.x * blockDim.x + threadIdx.x;
    if (i >= TT * DD * DD) return;
    int t = i >> 14;           // DD*DD = 16384
    int k = (i >> 7) & 127;
    float e = eemb[t * DD + k];
    int kn = i & (DD * DD - 1);
    wka[i] = e * wkwa[kn];
    wvt[i] = e * wv[kn];
}

// ---------------- tf32 tensor-core GEMM: [M,128] @ [128,128] ----------------
// CTA tile 128x128, 256 threads (8 warps, 4x2), warp tile 32x64, mma m16n8k8.
// MA: 0 plain A, 1 A scaled per-row, 2 relu(A*colscale+colshift)  (applied at smem store)
// MC: 0 C = acc, 1 C = res + acc + bias
// C may alias A: each block reads only A-rows [m0,m0+128) (all reads complete
// before the epilogue) and writes the same row range.
#define AS_LD 36
#define BS_LD 136
template<int MA, int MC>
__global__ void __launch_bounds__(256) gemm_tc(
    const float* __restrict__ A, const float* __restrict__ B, float* C, int M,
    long sAz, long sBz, long sCz,
    const float* __restrict__ rowscale, long sRSz,
    const float* __restrict__ ascale, const float* __restrict__ ashift,
    const float* res, const float* __restrict__ bias) {
    __shared__ unsigned As[128 * AS_LD];
    __shared__ unsigned Bs[32 * BS_LD];
    int z = blockIdx.z;
    A += (long)z * sAz; B += (long)z * sBz; C += (long)z * sCz;
    int tid = threadIdx.x;
    int warp = tid >> 5, lane = tid & 31;
    int wm = warp & 3, wn = warp >> 2;           // warp tile: rows wm*32, cols wn*64
    int r = lane >> 2, cq = lane & 3;
    int m0 = blockIdx.x * 128;

    // A loader: 2 threads per row, 16 floats each
    int arow = tid >> 1;
    int acol = (tid & 1) * 16;
    bool avalid = (m0 + arow) < M;
    float rs = 1.f;
    if (MA == 1) rs = avalid ? rowscale[(long)z * sRSz + m0 + arow] : 0.f;
    const float* Ap = A + (long)(m0 + arow) * DD + acol;
    // B loader: 32 rows x 128 cols per chunk, 16 floats/thread
    int brow = tid >> 3;
    int bcol = (tid & 7) * 16;
    const float* Bp = B + (long)brow * DD + bcol;

    float acc[2][8][4];
#pragma unroll
    for (int i = 0; i < 2; i++)
#pragma unroll
        for (int j = 0; j < 8; j++)
#pragma unroll
            for (int q = 0; q < 4; q++) acc[i][j][q] = 0.f;

    for (int k0 = 0; k0 < DD; k0 += 32) {
        // ---- stage A chunk [128 x 32] ----
        {
            float av[16];
            if (avalid) {
#pragma unroll
                for (int q = 0; q < 4; q++)
                    *(float4*)&av[q * 4] = *(const float4*)(Ap + k0 + q * 4);
                if (MA == 1) {
#pragma unroll
                    for (int j = 0; j < 16; j++) av[j] *= rs;
                }
                if (MA == 2) {
#pragma unroll
                    for (int j = 0; j < 16; j++) {
                        int c = k0 + acol + j;
                        av[j] = fmaxf(av[j] * ascale[c] + ashift[c], 0.f);
                    }
                }
            } else {
#pragma unroll
                for (int j = 0; j < 16; j++) av[j] = 0.f;
            }
            unsigned* dst = &As[arow * AS_LD + acol];
#pragma unroll
            for (int j = 0; j < 16; j++) dst[j] = f2tf32(av[j]);
        }
        // ---- stage B chunk [32 x 128] ----
        {
            float bv[16];
#pragma unroll
            for (int q = 0; q < 4; q++)
                *(float4*)&bv[q * 4] = *(const float4*)(Bp + (long)k0 * DD + q * 4);
            unsigned* dst = &Bs[brow * BS_LD + bcol];
#pragma unroll
            for (int j = 0; j < 16; j++) dst[j] = f2tf32(bv[j]);
        }
        __syncthreads();
#pragma unroll
        for (int kk = 0; kk < 32; kk += 8) {
            unsigned af[2][4];
#pragma unroll
            for (int i = 0; i < 2; i++) {
                int base = (wm * 32 + i * 16 + r) * AS_LD + kk + cq;
                af[i][0] = As[base];
                af[i][1] = As[base + 8 * AS_LD];
                af[i][2] = As[base + 4];
                af[i][3] = As[base + 8 * AS_LD + 4];
            }
#pragma unroll
            for (int j = 0; j < 8; j++) {
                int cb = wn * 64 + j * 8 + r;
                unsigned b0 = Bs[(kk + cq) * BS_LD + cb];
                unsigned b1 = Bs[(kk + cq + 4) * BS_LD + cb];
                mma_tf32(acc[0][j], af[0], b0, b1);
                mma_tf32(acc[1][j], af[1], b0, b1);
            }
        }
        __syncthreads();
    }

    // ---- epilogue: c0/c1 at (row, col..col+1), c2/c3 at (row+8, same cols) ----
#pragma unroll
    for (int i = 0; i < 2; i++) {
        int mr0 = m0 + wm * 32 + i * 16 + r;
#pragma unroll
        for (int h = 0; h < 2; h++) {
            int m = mr0 + h * 8;
            if (m >= M) continue;
            float* Crow = C + (long)m * DD;
            const float* Rrow = (MC == 1) ? res + (long)m * DD : nullptr;
#pragma unroll
            for (int j = 0; j < 8; j++) {
                int col = wn * 64 + j * 8 + cq * 2;
                float o0 = acc[i][j][h * 2 + 0];
                float o1 = acc[i][j][h * 2 + 1];
                if (MC == 1) {
                    float2 rr = *(const float2*)(Rrow + col);
                    o0 += rr.x + bias[col];
                    o1 += rr.y + bias[col + 1];
                }
                *(float2*)(Crow + col) = make_float2(o0, o1);
            }
        }
    }
}

// ---------------- host orchestration ----------------
extern "C" void kernel_launch(void* const* d_in, const int* in_sizes, int n_in,
                              void* d_out, int out_size) {
    const float* n_emb = (const float*)d_in[0];
    const float* e_emb = (const float*)d_in[1];
    const float* m_w1[2]    = {(const float*)d_in[2],  (const float*)d_in[14]};
    const float* m_gamma[2] = {(const float*)d_in[3],  (const float*)d_in[15]};
    const float* m_beta[2]  = {(const float*)d_in[4],  (const float*)d_in[16]};
    const float* m_w2[2]    = {(const float*)d_in[5],  (const float*)d_in[17]};
    const float* m_b2[2]    = {(const float*)d_in[6],  (const float*)d_in[18]};
    const float* a_wq[2] = {(const float*)d_in[7],  (const float*)d_in[19]};
    const float* a_wk[2] = {(const float*)d_in[8],  (const float*)d_in[20]};
    const float* a_wv[2] = {(const float*)d_in[9],  (const float*)d_in[21]};
    const float* a_wa[2] = {(const float*)d_in[10], (const float*)d_in[22]};
    const float* a_ba[2] = {(const float*)d_in[11], (const float*)d_in[23]};
    const float* a_wp[2] = {(const float*)d_in[12], (const float*)d_in[24]};
    const float* a_bp[2] = {(const float*)d_in[13], (const float*)d_in[25]};
    const int* node_ind = (const int*)d_in[26];
    const int* esrc = (const int*)d_in[27];
    const int* edst = (const int*)d_in[28];
    float* feat = (float*)d_out;

    float *pS, *pL, *pA, *pB, *pRdeg, *pBnacc, *pBnscale, *pBnshift, *pWkwa, *pWqaB, *pWkaB, *pWvtB;
    int* pDeg;
    cudaGetSymbolAddress((void**)&pS, g_S);
    cudaGetSymbolAddress((void**)&pL, g_Lg);
    cudaGetSymbolAddress((void**)&pA, g_bufA);
    cudaGetSymbolAddress((void**)&pB, g_bufB);
    cudaGetSymbolAddress((void**)&pDeg, g_deg);
    cudaGetSymbolAddress((void**)&pRdeg, g_rdeg);
    cudaGetSymbolAddress((void**)&pBnacc, g_bnacc);
    cudaGetSymbolAddress((void**)&pBnscale, g_bnscale);
    cudaGetSymbolAddress((void**)&pBnshift, g_bnshift);
    cudaGetSymbolAddress((void**)&pWkwa, g_wkwa);
    cudaGetSymbolAddress((void**)&pWqaB, g_wqa);
    cudaGetSymbolAddress((void**)&pWkaB, g_wka);
    cudaGetSymbolAddress((void**)&pWvtB, g_wvt);

    const int gElem  = (NND * 32 + 255) / 256;        // 12500
    const int gDeg   = (TT * EE + 255) / 256;
    const int gRdeg  = (TT * NND + 255) / 256;
    const int gScat  = (TT * EE * 32) / 256;          // 93750 (exact)
    const int gGemm  = (NND + 127) / 128;             // 782
    const int gBn    = (NND + 127) / 128;
    const int gSmx   = (int)((ND + 255) / 256);
    const int gWs    = (TT * DD * DD + 255) / 256;
    const size_t Sbytes = (size_t)TT * NND * DD * sizeof(float);

    // ---- init: feat = n_emb[node_ind]; degrees; e_emb passthrough output ----
    gather_kernel<<<gElem, 256>>>((const float4*)n_emb, node_ind, (float4*)feat);
    cudaMemcpyAsync(feat + ND, e_emb, TT * DD * sizeof(float), cudaMemcpyDeviceToDevice, 0);
    cudaMemsetAsync(pDeg, 0, TT * NND * sizeof(int), 0);
    deg_kernel<<<gDeg, 256>>>(edst, pDeg);
    rdeg_kernel<<<gRdeg, 256>>>(pDeg, pRdeg);

    // ---- precompute folded attention weights for both attn layers ----
    for (int l = 0; l < 2; l++) {
        float* pWqa = pWqaB + (long)l * DD * DD;
        float* pWka = pWkaB + (long)l * TT * DD * DD;
        float* pWvt = pWvtB + (long)l * TT * DD * DD;
        gemm_tc<0, 0><<<1, 256>>>(a_wq[l], a_wa[l], pWqa, DD, 0, 0, 0,
                                  nullptr, 0, nullptr, nullptr, nullptr, nullptr);
        gemm_tc<0, 0><<<1, 256>>>(a_wk[l], a_wa[l], pWkwa, DD, 0, 0, 0,
                                  nullptr, 0, nullptr, nullptr, nullptr, nullptr);
        wscale_kernel<<<gWs, 256>>>(e_emb, pWkwa, a_wv[l], pWka, pWvt);
    }

    // ---- 4 layers: GCN, attn, GCN, attn ----
    for (int l = 0; l < 2; l++) {
        // GCN layer l
        cudaMemsetAsync(pS, 0, Sbytes, 0);
        scatter_kernel<<<gScat, 256>>>((const float4*)feat, esrc, edst, pS);
        kform_kernel<<<gElem, 256>>>((const float4*)feat, (const float4*)pS, pDeg, pRdeg,
                                     (const float4*)e_emb, (float4*)pA);
        gemm_tc<0, 0><<<gGemm, 256>>>(pA, m_w1[l], pB, NND, 0, 0, 0,
                                      nullptr, 0, nullptr, nullptr, nullptr, nullptr);
        cudaMemsetAsync(pBnacc, 0, 2 * DD * sizeof(float), 0);
        bnstat_kernel<<<gBn, 128>>>(pB, NND, pBnacc);
        bnfin_kernel<<<1, 128>>>(pBnacc, m_gamma[l], m_beta[l], 1.0f / NND, pBnscale, pBnshift);
        gemm_tc<2, 1><<<gGemm, 256>>>(pB, m_w2[l], feat, NND, 0, 0, 0,
                                      nullptr, 0, pBnscale, pBnshift, feat, m_b2[l]);

        // attention layer l
        const float* pWqa = pWqaB + (long)l * DD * DD;
        const float* pWka = pWkaB + (long)l * TT * DD * DD;
        const float* pWvt = pWvtB + (long)l * TT * DD * DD;
        cudaMemsetAsync(pS, 0, Sbytes, 0);
        scatter_kernel<<<gScat, 256>>>((const float4*)feat, esrc, edst, pS);
        gemm_tc<0, 0><<<gGemm, 256>>>(feat, pWqa, pA, NND, 0, 0, 0,
                                      nullptr, 0, nullptr, nullptr, nullptr, nullptr);  // u
        dim3 gz(gGemm, 1, TT);
        // L_t first (reads S), then V_t in-place over S
        gemm_tc<1, 0><<<gz, 256>>>(pS, pWka, pL, NND, ND, (long)DD * DD, ND,
                                   pRdeg, NND, nullptr, nullptr, nullptr, nullptr);     // L_t
        gemm_tc<1, 0><<<gz, 256>>>(pS, pWvt, pS, NND, ND, (long)DD * DD, ND,
                                   pRdeg, NND, nullptr, nullptr, nullptr, nullptr);     // V_t (in-place)
        smx_kernel<<<gSmx, 256>>>(pA, pL, pS, a_ba[l], pB);                             // o
        gemm_tc<0, 1><<<gGemm, 256>>>(pB, a_wp[l], feat, NND, 0, 0, 0,
                                      nullptr, 0, nullptr, nullptr, feat, a_bp[l]);     // residual out
    }
}